// round 6
// baseline (speedup 1.0000x reference)
#include <cuda_runtime.h>
#include <cuda_bf16.h>

// ---------------------------------------------------------------------------
// Net_67765993996461  R6: mma.sync conv with 32co x 64n warp tiles (4 warps,
// 2 CTA/SM), tap-decomposed + double-buffered. Scalar-lane LIF kernels.
// Exact 3-way bf16 weight split (rel_err 0).
// ---------------------------------------------------------------------------

#define TAUF ((float)(10.0 / 7.0))

constexpr int BB   = 32;
constexpr int CC   = 64;
constexpr int TT_  = 129;
constexpr int TIN  = 128;
constexpr int MM   = 40;
constexpr int N_SP = TT_ * MM;        // 5160
constexpr int LANES = BB * CC * MM;   // 81920
constexpr int VOL   = BB * CC * N_SP;

constexpr int AP = 72;    // As row stride: LDSM conflict-free
constexpr int BP = 136;   // Bs row stride: LDSM conflict-free
constexpr int A_ELEMS = 192 * AP;
constexpr int B_ELEMS = 128 * BP;
constexpr int SMEM_BYTES = (2 * A_ELEMS + 2 * B_ELEMS) * 2;  // 90112

// Scratch
__device__ __nv_bfloat16 g_s1[VOL];
__device__ float         g_u [VOL];
__device__ __nv_bfloat16 g_s2[VOL];
__device__ __nv_bfloat16 g_w2s[12 * 3 * CC * CC];  // [tap][split][co][ci]
__device__ __nv_bfloat16 g_w3s[12 * 3 * CC * CC];
__device__ float         g_ssum[BB * CC * MM];

// ---------------------------------------------------------------------------
// conv1 + LIF: thread per (b,c,m), 4-row x 3-col register window, 3 LDG/t.
// ---------------------------------------------------------------------------
__global__ void conv1_lif_kernel(const float* __restrict__ x,
                                 const float* __restrict__ w1) {
    int idx = blockIdx.x * blockDim.x + threadIdx.x;
    if (idx >= LANES) return;
    int m = idx % MM;
    int c = (idx / MM) % CC;
    int b = idx / (MM * CC);

    float w[12];
#pragma unroll
    for (int k = 0; k < 12; k++) w[k] = w1[c * 12 + k];

    const float* xb = x + (size_t)b * TIN * MM;

    float a0[3], a1[3], a2[3], a3[3];
    auto load_row = [&](float* d, int t) {
        if (t >= 0 && t < TIN) {
            const float* r = xb + t * MM;
            d[0] = (m > 0)      ? r[m - 1] : 0.f;
            d[1] = r[m];
            d[2] = (m < MM - 1) ? r[m + 1] : 0.f;
        } else {
            d[0] = d[1] = d[2] = 0.f;
        }
    };
#pragma unroll
    for (int j = 0; j < 3; j++) { a0[j] = 0.f; a1[j] = 0.f; }
    load_row(a2, 0);
    load_row(a3, 1);

    __nv_bfloat16* sp = g_s1 + (size_t)(b * CC + c) * N_SP + m;
    float v = 0.f;
    for (int t = 0; t < TT_; t++) {
        float u = 0.f;
#pragma unroll
        for (int j = 0; j < 3; j++) {
            u += w[0 + j] * a0[j];
            u += w[3 + j] * a1[j];
            u += w[6 + j] * a2[j];
            u += w[9 + j] * a3[j];
        }
        v = v + (u - v) / TAUF;
        float s = (v >= 1.f) ? 1.f : 0.f;
        sp[t * MM] = __float2bfloat16(s);
        v = (v >= 1.f) ? 0.f : v;
#pragma unroll
        for (int j = 0; j < 3; j++) { a0[j] = a1[j]; a1[j] = a2[j]; a2[j] = a3[j]; }
        load_row(a3, t + 2);
    }
}

// ---------------------------------------------------------------------------
// Exact 3-way bf16 split for both conv weights in one launch.
// ---------------------------------------------------------------------------
__global__ void wsplit_kernel(const float* __restrict__ wa,
                              const float* __restrict__ wb) {
    int which = blockIdx.y;
    const float* w = which ? wb : wa;
    __nv_bfloat16* ws = which ? g_w3s : g_w2s;
    int i = blockIdx.x * blockDim.x + threadIdx.x;   // i = co*768 + ci*12 + tap
    if (i >= CC * CC * 12) return;
    int co  = i / 768;
    int r   = i - co * 768;
    int ci  = r / 12;
    int tap = r - ci * 12;
    float v = w[i];
    __nv_bfloat16 h0 = __float2bfloat16_rz(v);
    float r1 = v - __bfloat162float(h0);
    __nv_bfloat16 h1 = __float2bfloat16_rz(r1);
    float r2 = r1 - __bfloat162float(h1);
    __nv_bfloat16 h2 = __float2bfloat16_rz(r2);
    ws[((tap * 3 + 0) * CC + co) * CC + ci] = h0;
    ws[((tap * 3 + 1) * CC + co) * CC + ci] = h1;
    ws[((tap * 3 + 2) * CC + co) * CC + ci] = h2;
}

// ---------------------------------------------------------------------------
__device__ __forceinline__ void mma16816(float* d, const unsigned* a, const unsigned* b) {
    asm volatile(
        "mma.sync.aligned.m16n8k16.row.col.f32.bf16.bf16.f32 "
        "{%0,%1,%2,%3}, {%4,%5,%6,%7}, {%8,%9}, {%0,%1,%2,%3};\n"
        : "+f"(d[0]), "+f"(d[1]), "+f"(d[2]), "+f"(d[3])
        : "r"(a[0]), "r"(a[1]), "r"(a[2]), "r"(a[3]), "r"(b[0]), "r"(b[1]));
}
__device__ __forceinline__ void ldsm_x4(unsigned addr, unsigned& r0, unsigned& r1,
                                        unsigned& r2, unsigned& r3) {
    asm volatile("ldmatrix.sync.aligned.m8n8.x4.shared.b16 {%0,%1,%2,%3}, [%4];\n"
                 : "=r"(r0), "=r"(r1), "=r"(r2), "=r"(r3) : "r"(addr));
}
__device__ __forceinline__ void ldsm_x4_t(unsigned addr, unsigned& r0, unsigned& r1,
                                          unsigned& r2, unsigned& r3) {
    asm volatile("ldmatrix.sync.aligned.m8n8.x4.trans.shared.b16 {%0,%1,%2,%3}, [%4];\n"
                 : "=r"(r0), "=r"(r1), "=r"(r2), "=r"(r3) : "r"(addr));
}
__device__ __forceinline__ unsigned smem_u32(const void* p) {
    return (unsigned)__cvta_generic_to_shared(p);
}

// ---------------------------------------------------------------------------
// Tap-decomposed conv GEMM: 64co x 128n per CTA, 4 warps (32co x 64n each).
// ---------------------------------------------------------------------------
template <int LAYER, int DT, int PT, int DM, int PM>
__global__ __launch_bounds__(128, 2) void conv_mma_kernel() {
    extern __shared__ __nv_bfloat16 sm[];
    __nv_bfloat16* As = sm;                   // [2][192][AP]
    __nv_bfloat16* Bs = sm + 2 * A_ELEMS;     // [2][128][BP]

    const __nv_bfloat16* __restrict__ in = (LAYER == 2) ? g_s1 : g_s2;
    const __nv_bfloat16* __restrict__ ws = (LAYER == 2) ? g_w2s : g_w3s;

    int b  = blockIdx.y;
    int n0 = blockIdx.x * 128;
    int tid  = threadIdx.x;         // 0..127
    int warp = tid >> 5, lane = tid & 31;
    int wco = (warp >> 1) * 32;     // 0 or 32
    int wn  = (warp & 1) * 64;      // 0 or 64

    const __nv_bfloat16* inb = in + (size_t)b * CC * N_SP;

    // B gather: one n column per thread, all 64 ci
    int nl  = tid;
    int ng  = n0 + nl;
    int tt0 = ng / MM;
    int mm0 = ng - tt0 * MM;

    float acc[2][8][4];
#pragma unroll
    for (int i = 0; i < 2; i++)
#pragma unroll
        for (int j = 0; j < 8; j++)
#pragma unroll
            for (int q = 0; q < 4; q++) acc[i][j][q] = 0.f;

    const __nv_bfloat16 BZERO = __float2bfloat16(0.f);

    auto fill = [&](int tap, int sel) {
        // A: 192 rows x 64 ci = 1536 uint4, contiguous source
        const uint4* wsrc = (const uint4*)(ws + (size_t)tap * 3 * CC * CC);
        __nv_bfloat16* Ad = As + sel * A_ELEMS;
#pragma unroll
        for (int r = 0; r < 12; r++) {
            int i = tid + r * 128;
            int row = i >> 3, q = i & 7;
            *(uint4*)(Ad + row * AP + q * 8) = wsrc[i];
        }
        // B: shifted-plane gather, predicate fixed per (thread, tap)
        int kt = tap / 3, km = tap - kt * 3;
        int tt = tt0 + DT * kt - PT;
        int mm = mm0 + DM * km - PM;
        bool p = (tt >= 0) & (tt < TT_) & (mm >= 0) & (mm < MM);
        const __nv_bfloat16* src = inb + (tt * MM + mm);
        __nv_bfloat16* Bd = Bs + sel * B_ELEMS + nl;
        if (p) {
#pragma unroll 8
            for (int c = 0; c < 64; c++) Bd[c * BP] = src[(size_t)c * N_SP];
        } else {
#pragma unroll 8
            for (int c = 0; c < 64; c++) Bd[c * BP] = BZERO;
        }
    };

    auto domma = [&](int sel) {
        const __nv_bfloat16* Ab = As + sel * A_ELEMS;
        const __nv_bfloat16* Bb = Bs + sel * B_ELEMS;
#pragma unroll
        for (int ks = 0; ks < 4; ks++) {
            int k0 = ks * 16;
            unsigned bf[8][2];
#pragma unroll
            for (int g = 0; g < 4; g++) {
                unsigned addr = smem_u32(Bb + (wn + g * 16 + (lane >> 4) * 8) * BP +
                                         0 /*row-major [n][k]*/);
                // rows = n? No: Bs is [n][k]; trans ldsm wants 16 k?? keep R3 form:
                addr = smem_u32(Bb + (k0 + (lane & 15)) * 0 + 0);
                (void)addr;
                unsigned a2 = smem_u32(Bb + (size_t)0);
                (void)a2;
                // (computed below properly)
                unsigned q0, q1, q2, q3;
                unsigned real_addr = smem_u32(Bb + (size_t)(wn + g * 16 + 0) * 0);
                (void)real_addr;
                // R3-verified addressing: row = n (16B chunks along k)
                unsigned addr3 = smem_u32(Bb + (size_t)(k0 + (lane & 15)) * BP +
                                          wn + g * 16 + (lane >> 4) * 8);
                // NOTE: R3 layout is Bs[n][k]; its verified trans-ldsm address was
                // Bb + (k0 + lane15)*BP + wn + ... with BP the [n]-row stride, i.e.
                // rows indexed by k? That passed rel_err 0 in R3; replicate exactly.
                ldsm_x4_t(addr3, q0, q1, q2, q3);
                bf[2 * g][0] = q0; bf[2 * g][1] = q1;
                bf[2 * g + 1][0] = q2; bf[2 * g + 1][1] = q3;
            }
#pragma unroll
            for (int s = 0; s < 3; s++) {
#pragma unroll
                for (int mf = 0; mf < 2; mf++) {
                    unsigned addr = smem_u32(Ab + (size_t)(s * 64 + wco + mf * 16 + (lane & 15)) * AP +
                                             k0 + (lane >> 4) * 8);
                    unsigned a[4];
                    ldsm_x4(addr, a[0], a[1], a[2], a[3]);
#pragma unroll
                    for (int nf = 0; nf < 8; nf++)
                        mma16816(acc[mf][nf], a, bf[nf]);
                }
            }
        }
    };

    fill(0, 0);
    __syncthreads();
#pragma unroll 1
    for (int tap = 0; tap < 12; tap++) {
        domma(tap & 1);
        if (tap < 11) fill(tap + 1, (tap + 1) & 1);
        __syncthreads();
    }

    int lrow = lane >> 2, lk = (lane & 3) * 2;
    float* outb = g_u + (size_t)b * CC * N_SP;
#pragma unroll
    for (int mf = 0; mf < 2; mf++) {
#pragma unroll
        for (int nf = 0; nf < 8; nf++) {
            int co = wco + mf * 16 + lrow;
            int n  = n0 + wn + nf * 8 + lk;
            float* p1 = outb + (size_t)co * N_SP + n;
            float* p2 = outb + (size_t)(co + 8) * N_SP + n;
            if (n + 1 < N_SP) {
                *(float2*)p1 = make_float2(acc[mf][nf][0], acc[mf][nf][1]);
                *(float2*)p2 = make_float2(acc[mf][nf][2], acc[mf][nf][3]);
            } else if (n < N_SP) {
                p1[0] = acc[mf][nf][0];
                p2[0] = acc[mf][nf][2];
            }
        }
    }
}

// ---------------------------------------------------------------------------
// LIF over t, scalar thread per (b,c,m). Writes bf16 spikes to g_s2.
// ---------------------------------------------------------------------------
__global__ void lif2_kernel() {
    int idx = blockIdx.x * blockDim.x + threadIdx.x;
    if (idx >= LANES) return;
    int m = idx % MM;
    int bc = idx / MM;
    const float* up = g_u + (size_t)bc * N_SP + m;
    __nv_bfloat16* sp = g_s2 + (size_t)bc * N_SP + m;
    float v = 0.f;
    for (int t = 0; t < TT_; t++) {
        float xx = up[t * MM];
        v = v + (xx - v) / TAUF;
        float sv = (v >= 1.f) ? 1.f : 0.f;
        sp[t * MM] = __float2bfloat16(sv);
        v = (v >= 1.f) ? 0.f : v;
    }
}

// ---------------------------------------------------------------------------
// LIF3 fused with time-sum: writes g_ssum directly (no spike buffer).
// ---------------------------------------------------------------------------
__global__ void lif3_tsum_kernel() {
    int idx = blockIdx.x * blockDim.x + threadIdx.x;
    if (idx >= LANES) return;
    int m = idx % MM;
    int bc = idx / MM;
    const float* up = g_u + (size_t)bc * N_SP + m;
    float v = 0.f, a = 0.f;
    for (int t = 0; t < TT_; t++) {
        float xx = up[t * MM];
        v = v + (xx - v) / TAUF;
        if (v >= 1.f) { a += 1.f; v = 0.f; }
    }
    g_ssum[(size_t)bc * MM + m] = a;
}

// ---------------------------------------------------------------------------
__global__ void fc_kernel(const float* __restrict__ wf,
                          const float* __restrict__ bf,
                          float* __restrict__ y) {
    int b = blockIdx.x, j = blockIdx.y;
    int tid = threadIdx.x;
    const float* sb = g_ssum + b * (CC * MM);
    const float* wj = wf + j * (CC * MM);
    float acc = 0.f;
    for (int i = tid; i < CC * MM; i += 128) acc += sb[i] * wj[i];
    __shared__ float red[128];
    red[tid] = acc;
    __syncthreads();
    for (int s = 64; s > 0; s >>= 1) {
        if (tid < s) red[tid] += red[tid + s];
        __syncthreads();
    }
    if (tid == 0) y[b * 12 + j] = red[0] * (1.0f / 129.0f) + bf[j];
}

// ---------------------------------------------------------------------------
extern "C" void kernel_launch(void* const* d_in, const int* in_sizes, int n_in,
                              void* d_out, int out_size) {
    const float* x  = (const float*)d_in[0];
    const float* w1 = (const float*)d_in[1];
    const float* w2 = (const float*)d_in[2];
    const float* w3 = (const float*)d_in[3];
    const float* wf = (const float*)d_in[4];
    const float* bf = (const float*)d_in[5];
    float* y = (float*)d_out;

    static int smem_set = 0;
    if (!smem_set) {
        cudaFuncSetAttribute(conv_mma_kernel<2, 4, 6, 3, 3>,
                             cudaFuncAttributeMaxDynamicSharedMemorySize, SMEM_BYTES);
        cudaFuncSetAttribute(conv_mma_kernel<3, 16, 24, 9, 9>,
                             cudaFuncAttributeMaxDynamicSharedMemorySize, SMEM_BYTES);
        smem_set = 1;
    }

    {
        dim3 grid((CC * CC * 12 + 255) / 256, 2);
        wsplit_kernel<<<grid, 256>>>(w2, w3);
    }

    conv1_lif_kernel<<<(LANES + 255) / 256, 256>>>(x, w1);

    {
        dim3 grid((N_SP + 127) / 128, BB);
        conv_mma_kernel<2, 4, 6, 3, 3><<<grid, 128, SMEM_BYTES>>>();
    }
    lif2_kernel<<<(LANES + 255) / 256, 256>>>();

    {
        dim3 grid((N_SP + 127) / 128, BB);
        conv_mma_kernel<3, 16, 24, 9, 9><<<grid, 128, SMEM_BYTES>>>();
    }
    lif3_tsum_kernel<<<(LANES + 255) / 256, 256>>>();

    {
        dim3 grid(BB, 12);
        fc_kernel<<<grid, 128>>>(wf, bf, y);
    }
}

// round 7
// speedup vs baseline: 2.0539x; 2.0539x over previous
#include <cuda_runtime.h>
#include <cuda_bf16.h>

// ---------------------------------------------------------------------------
// Net_67765993996461  R7: R3 conv kernels restored verbatim (proven fastest on
// the available mma.sync path) + MLP-unrolled LIF side kernels, fused
// lif3+tsum, windowed conv1, single wsplit launch.
// ---------------------------------------------------------------------------

#define TAUF ((float)(10.0 / 7.0))

constexpr int BB   = 32;
constexpr int CC   = 64;
constexpr int TT_  = 129;
constexpr int TIN  = 128;
constexpr int MM   = 40;
constexpr int N_SP = TT_ * MM;        // 5160
constexpr int LANES = BB * CC * MM;   // 81920
constexpr int VOL   = BB * CC * N_SP;

constexpr int AP = 72;    // As row stride: LDSM conflict-free
constexpr int BP = 136;   // Bs row stride: LDSM conflict-free
constexpr int SMEM_BYTES = (2 * 192 * AP + 2 * 64 * BP) * 2;  // 90112

// Scratch
__device__ __nv_bfloat16 g_s1[VOL];
__device__ float         g_u [VOL];
__device__ __nv_bfloat16 g_s2[VOL];
__device__ __nv_bfloat16 g_w2s[12 * 3 * CC * CC];  // [tap][split][co][ci]
__device__ __nv_bfloat16 g_w3s[12 * 3 * CC * CC];
__device__ float         g_ssum[BB * CC * MM];

// ---------------------------------------------------------------------------
// conv1 + LIF: thread per (b,c,m), 4x3 register window, 3 LDG per t-step.
// ---------------------------------------------------------------------------
__global__ void conv1_lif_kernel(const float* __restrict__ x,
                                 const float* __restrict__ w1) {
    int idx = blockIdx.x * blockDim.x + threadIdx.x;
    if (idx >= LANES) return;
    int m = idx % MM;
    int c = (idx / MM) % CC;
    int b = idx / (MM * CC);

    float w[12];
#pragma unroll
    for (int k = 0; k < 12; k++) w[k] = w1[c * 12 + k];

    const float* xb = x + (size_t)b * TIN * MM;

    float a0[3], a1[3], a2[3], a3[3];
    auto load_row = [&](float* d, int t) {
        if (t >= 0 && t < TIN) {
            const float* r = xb + t * MM;
            d[0] = (m > 0)      ? r[m - 1] : 0.f;
            d[1] = r[m];
            d[2] = (m < MM - 1) ? r[m + 1] : 0.f;
        } else {
            d[0] = d[1] = d[2] = 0.f;
        }
    };
#pragma unroll
    for (int j = 0; j < 3; j++) { a0[j] = 0.f; a1[j] = 0.f; }
    load_row(a2, 0);
    load_row(a3, 1);

    __nv_bfloat16* sp = g_s1 + (size_t)(b * CC + c) * N_SP + m;
    float v = 0.f;
    for (int t = 0; t < TT_; t++) {
        float u = 0.f;
#pragma unroll
        for (int j = 0; j < 3; j++) {
            u += w[0 + j] * a0[j];
            u += w[3 + j] * a1[j];
            u += w[6 + j] * a2[j];
            u += w[9 + j] * a3[j];
        }
        v = v + (u - v) / TAUF;
        float s = (v >= 1.f) ? 1.f : 0.f;
        sp[t * MM] = __float2bfloat16(s);
        v = (v >= 1.f) ? 0.f : v;
#pragma unroll
        for (int j = 0; j < 3; j++) { a0[j] = a1[j]; a1[j] = a2[j]; a2[j] = a3[j]; }
        load_row(a3, t + 2);
    }
}

// ---------------------------------------------------------------------------
// Exact 3-way bf16 split for both conv weights in one launch.
// ---------------------------------------------------------------------------
__global__ void wsplit_kernel(const float* __restrict__ wa,
                              const float* __restrict__ wb) {
    int which = blockIdx.y;
    const float* w = which ? wb : wa;
    __nv_bfloat16* ws = which ? g_w3s : g_w2s;
    int i = blockIdx.x * blockDim.x + threadIdx.x;   // i = co*768 + ci*12 + tap
    if (i >= CC * CC * 12) return;
    int co  = i / 768;
    int r   = i - co * 768;
    int ci  = r / 12;
    int tap = r - ci * 12;
    float v = w[i];
    __nv_bfloat16 h0 = __float2bfloat16_rz(v);
    float r1 = v - __bfloat162float(h0);
    __nv_bfloat16 h1 = __float2bfloat16_rz(r1);
    float r2 = r1 - __bfloat162float(h1);
    __nv_bfloat16 h2 = __float2bfloat16_rz(r2);
    ws[((tap * 3 + 0) * CC + co) * CC + ci] = h0;
    ws[((tap * 3 + 1) * CC + co) * CC + ci] = h1;
    ws[((tap * 3 + 2) * CC + co) * CC + ci] = h2;
}

// ---------------------------------------------------------------------------
__device__ __forceinline__ void mma16816(float* d, const unsigned* a, const unsigned* b) {
    asm volatile(
        "mma.sync.aligned.m16n8k16.row.col.f32.bf16.bf16.f32 "
        "{%0,%1,%2,%3}, {%4,%5,%6,%7}, {%8,%9}, {%0,%1,%2,%3};\n"
        : "+f"(d[0]), "+f"(d[1]), "+f"(d[2]), "+f"(d[3])
        : "r"(a[0]), "r"(a[1]), "r"(a[2]), "r"(a[3]), "r"(b[0]), "r"(b[1]));
}
__device__ __forceinline__ void ldsm_x4(unsigned addr, unsigned& r0, unsigned& r1,
                                        unsigned& r2, unsigned& r3) {
    asm volatile("ldmatrix.sync.aligned.m8n8.x4.shared.b16 {%0,%1,%2,%3}, [%4];\n"
                 : "=r"(r0), "=r"(r1), "=r"(r2), "=r"(r3) : "r"(addr));
}
__device__ __forceinline__ void ldsm_x4_t(unsigned addr, unsigned& r0, unsigned& r1,
                                          unsigned& r2, unsigned& r3) {
    asm volatile("ldmatrix.sync.aligned.m8n8.x4.trans.shared.b16 {%0,%1,%2,%3}, [%4];\n"
                 : "=r"(r0), "=r"(r1), "=r"(r2), "=r"(r3) : "r"(addr));
}
__device__ __forceinline__ unsigned smem_u32(const void* p) {
    return (unsigned)__cvta_generic_to_shared(p);
}

// ---------------------------------------------------------------------------
// R3 conv kernel (verbatim): 64co x 128n per CTA, 8 warps (32co x 32n each),
// tap-decomposed, double-buffered.
// ---------------------------------------------------------------------------
template <int LAYER, int DT, int PT, int DM, int PM>
__global__ __launch_bounds__(256, 2) void conv_mma_kernel() {
    extern __shared__ __nv_bfloat16 sm[];
    __nv_bfloat16* As = sm;                  // [2][3*64][AP]
    __nv_bfloat16* Bs = sm + 2 * 192 * AP;   // [2][64][BP]

    const __nv_bfloat16* __restrict__ in = (LAYER == 2) ? g_s1 : g_s2;
    const __nv_bfloat16* __restrict__ ws = (LAYER == 2) ? g_w2s : g_w3s;

    int b  = blockIdx.y;
    int n0 = blockIdx.x * 128;
    int tid  = threadIdx.x;
    int warp = tid >> 5, lane = tid & 31;
    int wco = (warp >> 2) * 32;
    int wn  = (warp & 3) * 32;

    const __nv_bfloat16* inb = in + (size_t)b * CC * N_SP;

    int nl   = tid & 127;
    int half = tid >> 7;
    int ng  = n0 + nl;
    int tt0 = ng / MM;
    int mm0 = ng - tt0 * MM;

    float acc[2][4][4];
#pragma unroll
    for (int i = 0; i < 2; i++)
#pragma unroll
        for (int j = 0; j < 4; j++)
#pragma unroll
            for (int q = 0; q < 4; q++) acc[i][j][q] = 0.f;

    const __nv_bfloat16 BZERO = __float2bfloat16(0.f);

    auto fill = [&](int tap, int sel) {
        const uint4* wsrc = (const uint4*)(ws + (size_t)tap * 3 * CC * CC);
        __nv_bfloat16* Ad = As + sel * 192 * AP;
#pragma unroll
        for (int r = 0; r < 6; r++) {
            int i = tid + r * 256;
            int row = i >> 3, q = i & 7;
            *(uint4*)(Ad + row * AP + q * 8) = wsrc[i];
        }
        int kt = tap / 3, km = tap - kt * 3;
        int toff = DT * kt - PT, moff = DM * km - PM;
        int tt = tt0 + toff, mm = mm0 + moff;
        bool p = (tt >= 0) & (tt < TT_) & (mm >= 0) & (mm < MM);
        const __nv_bfloat16* src = inb + (size_t)(half * 32) * N_SP + (tt * MM + mm);
        __nv_bfloat16* Bd = Bs + sel * 64 * BP + (half * 32) * BP + nl;
        if (p) {
#pragma unroll
            for (int c = 0; c < 32; c++) Bd[c * BP] = src[(size_t)c * N_SP];
        } else {
#pragma unroll
            for (int c = 0; c < 32; c++) Bd[c * BP] = BZERO;
        }
    };

    auto domma = [&](int sel) {
        const __nv_bfloat16* Ab = As + sel * 192 * AP;
        const __nv_bfloat16* Bb = Bs + sel * 64 * BP;
#pragma unroll
        for (int ks = 0; ks < 4; ks++) {
            int k0 = ks * 16;
            unsigned bf[4][2];
#pragma unroll
            for (int g = 0; g < 2; g++) {
                unsigned addr = smem_u32(Bb + (k0 + (lane & 15)) * BP +
                                         wn + g * 16 + (lane >> 4) * 8);
                unsigned r0, r1, r2, r3;
                ldsm_x4_t(addr, r0, r1, r2, r3);
                bf[2 * g][0] = r0; bf[2 * g][1] = r1;
                bf[2 * g + 1][0] = r2; bf[2 * g + 1][1] = r3;
            }
#pragma unroll
            for (int s = 0; s < 3; s++) {
#pragma unroll
                for (int mf = 0; mf < 2; mf++) {
                    unsigned addr = smem_u32(Ab + (s * 64 + wco + mf * 16 + (lane & 15)) * AP +
                                             k0 + (lane >> 4) * 8);
                    unsigned a[4];
                    ldsm_x4(addr, a[0], a[1], a[2], a[3]);
#pragma unroll
                    for (int nf = 0; nf < 4; nf++)
                        mma16816(acc[mf][nf], a, bf[nf]);
                }
            }
        }
    };

    fill(0, 0);
    __syncthreads();
#pragma unroll
    for (int tap = 0; tap < 12; tap++) {
        domma(tap & 1);
        if (tap < 11) fill(tap + 1, (tap + 1) & 1);
        __syncthreads();
    }

    int lrow = lane >> 2, lk = (lane & 3) * 2;
    float* outb = g_u + (size_t)b * CC * N_SP;
#pragma unroll
    for (int mf = 0; mf < 2; mf++) {
#pragma unroll
        for (int nf = 0; nf < 4; nf++) {
            int co = wco + mf * 16 + lrow;
            int n  = n0 + wn + nf * 8 + lk;
            float* p1 = outb + (size_t)co * N_SP + n;
            float* p2 = outb + (size_t)(co + 8) * N_SP + n;
            if (n + 1 < N_SP) {
                *(float2*)p1 = make_float2(acc[mf][nf][0], acc[mf][nf][1]);
                *(float2*)p2 = make_float2(acc[mf][nf][2], acc[mf][nf][3]);
            } else if (n < N_SP) {
                p1[0] = acc[mf][nf][0];
                p2[0] = acc[mf][nf][2];
            }
        }
    }
}

// ---------------------------------------------------------------------------
// LIF over t with MLP=4 load batching. Writes bf16 spikes to g_s2.
// ---------------------------------------------------------------------------
__global__ void lif2_kernel() {
    int idx = blockIdx.x * blockDim.x + threadIdx.x;
    if (idx >= LANES) return;
    int m = idx % MM;
    int bc = idx / MM;
    const float* up = g_u + (size_t)bc * N_SP + m;
    __nv_bfloat16* sp = g_s2 + (size_t)bc * N_SP + m;
    float v = 0.f;
#pragma unroll 1
    for (int t = 0; t < 128; t += 4) {
        float x0 = up[(t + 0) * MM];
        float x1 = up[(t + 1) * MM];
        float x2 = up[(t + 2) * MM];
        float x3 = up[(t + 3) * MM];
        v = v + (x0 - v) / TAUF;
        float s0 = (v >= 1.f) ? 1.f : 0.f;
        v = (v >= 1.f) ? 0.f : v;
        v = v + (x1 - v) / TAUF;
        float s1 = (v >= 1.f) ? 1.f : 0.f;
        v = (v >= 1.f) ? 0.f : v;
        v = v + (x2 - v) / TAUF;
        float s2 = (v >= 1.f) ? 1.f : 0.f;
        v = (v >= 1.f) ? 0.f : v;
        v = v + (x3 - v) / TAUF;
        float s3 = (v >= 1.f) ? 1.f : 0.f;
        v = (v >= 1.f) ? 0.f : v;
        sp[(t + 0) * MM] = __float2bfloat16(s0);
        sp[(t + 1) * MM] = __float2bfloat16(s1);
        sp[(t + 2) * MM] = __float2bfloat16(s2);
        sp[(t + 3) * MM] = __float2bfloat16(s3);
    }
    {   // t = 128
        float x0 = up[128 * MM];
        v = v + (x0 - v) / TAUF;
        float s0 = (v >= 1.f) ? 1.f : 0.f;
        sp[128 * MM] = __float2bfloat16(s0);
    }
}

// ---------------------------------------------------------------------------
// LIF3 fused with time-sum (MLP=4): writes g_ssum directly.
// ---------------------------------------------------------------------------
__global__ void lif3_tsum_kernel() {
    int idx = blockIdx.x * blockDim.x + threadIdx.x;
    if (idx >= LANES) return;
    int m = idx % MM;
    int bc = idx / MM;
    const float* up = g_u + (size_t)bc * N_SP + m;
    float v = 0.f, a = 0.f;
#pragma unroll 1
    for (int t = 0; t < 128; t += 4) {
        float x0 = up[(t + 0) * MM];
        float x1 = up[(t + 1) * MM];
        float x2 = up[(t + 2) * MM];
        float x3 = up[(t + 3) * MM];
        v = v + (x0 - v) / TAUF;
        if (v >= 1.f) { a += 1.f; v = 0.f; }
        v = v + (x1 - v) / TAUF;
        if (v >= 1.f) { a += 1.f; v = 0.f; }
        v = v + (x2 - v) / TAUF;
        if (v >= 1.f) { a += 1.f; v = 0.f; }
        v = v + (x3 - v) / TAUF;
        if (v >= 1.f) { a += 1.f; v = 0.f; }
    }
    {
        float x0 = up[128 * MM];
        v = v + (x0 - v) / TAUF;
        if (v >= 1.f) a += 1.f;
    }
    g_ssum[(size_t)bc * MM + m] = a;
}

// ---------------------------------------------------------------------------
__global__ void fc_kernel(const float* __restrict__ wf,
                          const float* __restrict__ bf,
                          float* __restrict__ y) {
    int b = blockIdx.x, j = blockIdx.y;
    int tid = threadIdx.x;
    const float* sb = g_ssum + b * (CC * MM);
    const float* wj = wf + j * (CC * MM);
    float acc = 0.f;
    for (int i = tid; i < CC * MM; i += 128) acc += sb[i] * wj[i];
    __shared__ float red[128];
    red[tid] = acc;
    __syncthreads();
    for (int s = 64; s > 0; s >>= 1) {
        if (tid < s) red[tid] += red[tid + s];
        __syncthreads();
    }
    if (tid == 0) y[b * 12 + j] = red[0] * (1.0f / 129.0f) + bf[j];
}

// ---------------------------------------------------------------------------
extern "C" void kernel_launch(void* const* d_in, const int* in_sizes, int n_in,
                              void* d_out, int out_size) {
    const float* x  = (const float*)d_in[0];
    const float* w1 = (const float*)d_in[1];
    const float* w2 = (const float*)d_in[2];
    const float* w3 = (const float*)d_in[3];
    const float* wf = (const float*)d_in[4];
    const float* bf = (const float*)d_in[5];
    float* y = (float*)d_out;

    static int smem_set = 0;
    if (!smem_set) {
        cudaFuncSetAttribute(conv_mma_kernel<2, 4, 6, 3, 3>,
                             cudaFuncAttributeMaxDynamicSharedMemorySize, SMEM_BYTES);
        cudaFuncSetAttribute(conv_mma_kernel<3, 16, 24, 9, 9>,
                             cudaFuncAttributeMaxDynamicSharedMemorySize, SMEM_BYTES);
        smem_set = 1;
    }

    {
        dim3 grid((CC * CC * 12 + 255) / 256, 2);
        wsplit_kernel<<<grid, 256>>>(w2, w3);
    }

    conv1_lif_kernel<<<(LANES + 255) / 256, 256>>>(x, w1);

    {
        dim3 grid((N_SP + 127) / 128, BB);
        conv_mma_kernel<2, 4, 6, 3, 3><<<grid, 256, SMEM_BYTES>>>();
    }
    lif2_kernel<<<(LANES + 255) / 256, 256>>>();

    {
        dim3 grid((N_SP + 127) / 128, BB);
        conv_mma_kernel<3, 16, 24, 9, 9><<<grid, 256, SMEM_BYTES>>>();
    }
    lif3_tsum_kernel<<<(LANES + 255) / 256, 256>>>();

    {
        dim3 grid(BB, 12);
        fc_kernel<<<grid, 128>>>(wf, bf, y);
    }
}

// round 9
// speedup vs baseline: 2.1542x; 1.0488x over previous
#include <cuda_runtime.h>
#include <cuda_bf16.h>

// ---------------------------------------------------------------------------
// Net_67765993996461  R9: R8 with the B-fill base-offset bug fixed.
// conv = swizzled pad-free tiles, A double-buffered via cp.async, B single-
// buffered, 64KB smem -> 3 CTAs/SM. LIF kernels MLP=8. Exact 3-way bf16 split.
// ---------------------------------------------------------------------------

#define TAUF ((float)(10.0 / 7.0))

constexpr int BB   = 32;
constexpr int CC   = 64;
constexpr int TT_  = 129;
constexpr int TIN  = 128;
constexpr int MM   = 40;
constexpr int N_SP = TT_ * MM;        // 5160
constexpr int LANES = BB * CC * MM;   // 81920
constexpr int VOL   = BB * CC * N_SP;

// conv smem: A = 2 x 192 rows x 128B (swizzled), B = 64 rows x 256B (swizzled)
constexpr int A_TILE = 192 * 128;              // 24576 B per buffer
constexpr int B_OFF  = 2 * A_TILE;             // 49152
constexpr int SMEM_BYTES = B_OFF + 64 * 256;   // 65536 B total

// Scratch
__device__ __nv_bfloat16 g_s1[VOL];
__device__ float         g_u [VOL];
__device__ __nv_bfloat16 g_s2[VOL];
__device__ __nv_bfloat16 g_w2s[12 * 3 * CC * CC];  // [tap][split][co][ci]
__device__ __nv_bfloat16 g_w3s[12 * 3 * CC * CC];
__device__ float         g_ssum[BB * CC * MM];

// ---------------------------------------------------------------------------
// conv1 + LIF: thread per (b,c,m), 4x3 register window, 3 LDG per t-step.
// ---------------------------------------------------------------------------
__global__ void conv1_lif_kernel(const float* __restrict__ x,
                                 const float* __restrict__ w1) {
    int idx = blockIdx.x * blockDim.x + threadIdx.x;
    if (idx >= LANES) return;
    int m = idx % MM;
    int c = (idx / MM) % CC;
    int b = idx / (MM * CC);

    float w[12];
#pragma unroll
    for (int k = 0; k < 12; k++) w[k] = w1[c * 12 + k];

    const float* xb = x + (size_t)b * TIN * MM;

    float a0[3], a1[3], a2[3], a3[3];
    auto load_row = [&](float* d, int t) {
        if (t >= 0 && t < TIN) {
            const float* r = xb + t * MM;
            d[0] = (m > 0)      ? r[m - 1] : 0.f;
            d[1] = r[m];
            d[2] = (m < MM - 1) ? r[m + 1] : 0.f;
        } else {
            d[0] = d[1] = d[2] = 0.f;
        }
    };
#pragma unroll
    for (int j = 0; j < 3; j++) { a0[j] = 0.f; a1[j] = 0.f; }
    load_row(a2, 0);
    load_row(a3, 1);

    __nv_bfloat16* sp = g_s1 + (size_t)(b * CC + c) * N_SP + m;
    float v = 0.f;
    for (int t = 0; t < TT_; t++) {
        float u = 0.f;
#pragma unroll
        for (int j = 0; j < 3; j++) {
            u += w[0 + j] * a0[j];
            u += w[3 + j] * a1[j];
            u += w[6 + j] * a2[j];
            u += w[9 + j] * a3[j];
        }
        v = v + (u - v) / TAUF;
        float s = (v >= 1.f) ? 1.f : 0.f;
        sp[t * MM] = __float2bfloat16(s);
        v = (v >= 1.f) ? 0.f : v;
#pragma unroll
        for (int j = 0; j < 3; j++) { a0[j] = a1[j]; a1[j] = a2[j]; a2[j] = a3[j]; }
        load_row(a3, t + 2);
    }
}

// ---------------------------------------------------------------------------
// Exact 3-way bf16 split for both conv weights in one launch.
// ---------------------------------------------------------------------------
__global__ void wsplit_kernel(const float* __restrict__ wa,
                              const float* __restrict__ wb) {
    int which = blockIdx.y;
    const float* w = which ? wb : wa;
    __nv_bfloat16* ws = which ? g_w3s : g_w2s;
    int i = blockIdx.x * blockDim.x + threadIdx.x;   // i = co*768 + ci*12 + tap
    if (i >= CC * CC * 12) return;
    int co  = i / 768;
    int r   = i - co * 768;
    int ci  = r / 12;
    int tap = r - ci * 12;
    float v = w[i];
    __nv_bfloat16 h0 = __float2bfloat16_rz(v);
    float r1 = v - __bfloat162float(h0);
    __nv_bfloat16 h1 = __float2bfloat16_rz(r1);
    float r2 = r1 - __bfloat162float(h1);
    __nv_bfloat16 h2 = __float2bfloat16_rz(r2);
    ws[((tap * 3 + 0) * CC + co) * CC + ci] = h0;
    ws[((tap * 3 + 1) * CC + co) * CC + ci] = h1;
    ws[((tap * 3 + 2) * CC + co) * CC + ci] = h2;
}

// ---------------------------------------------------------------------------
__device__ __forceinline__ void mma16816(float* d, const unsigned* a, const unsigned* b) {
    asm volatile(
        "mma.sync.aligned.m16n8k16.row.col.f32.bf16.bf16.f32 "
        "{%0,%1,%2,%3}, {%4,%5,%6,%7}, {%8,%9}, {%0,%1,%2,%3};\n"
        : "+f"(d[0]), "+f"(d[1]), "+f"(d[2]), "+f"(d[3])
        : "r"(a[0]), "r"(a[1]), "r"(a[2]), "r"(a[3]), "r"(b[0]), "r"(b[1]));
}
__device__ __forceinline__ void ldsm_x4(unsigned addr, unsigned& r0, unsigned& r1,
                                        unsigned& r2, unsigned& r3) {
    asm volatile("ldmatrix.sync.aligned.m8n8.x4.shared.b16 {%0,%1,%2,%3}, [%4];\n"
                 : "=r"(r0), "=r"(r1), "=r"(r2), "=r"(r3) : "r"(addr));
}
__device__ __forceinline__ void ldsm_x4_t(unsigned addr, unsigned& r0, unsigned& r1,
                                          unsigned& r2, unsigned& r3) {
    asm volatile("ldmatrix.sync.aligned.m8n8.x4.trans.shared.b16 {%0,%1,%2,%3}, [%4];\n"
                 : "=r"(r0), "=r"(r1), "=r"(r2), "=r"(r3) : "r"(addr));
}
__device__ __forceinline__ unsigned smem_u32(const void* p) {
    return (unsigned)__cvta_generic_to_shared(p);
}
__device__ __forceinline__ void cp_async16(unsigned dst, const void* src) {
    asm volatile("cp.async.cg.shared.global [%0], [%1], 16;\n"
                 :: "r"(dst), "l"(src) : "memory");
}
#define CP_COMMIT() asm volatile("cp.async.commit_group;\n" ::: "memory")
#define CP_WAIT1()  asm volatile("cp.async.wait_group 1;\n" ::: "memory")
#define CP_WAIT0()  asm volatile("cp.async.wait_group 0;\n" ::: "memory")

// ---------------------------------------------------------------------------
// Conv GEMM: 64co x 128n per CTA, 8 warps (32co x 32n), tap-decomposed.
// A (weights, 192 rows x 128B, XOR-swizzled): double-buffered via cp.async.
// B (spikes,  64 rows x 256B, XOR-swizzled): single-buffered.
// ---------------------------------------------------------------------------
template <int LAYER, int DT, int PT, int DM, int PM>
__global__ __launch_bounds__(256, 3) void conv_mma_kernel() {
    extern __shared__ __align__(128) char sm[];
    unsigned sbase = smem_u32(sm);
    unsigned Ab0 = sbase;
    unsigned Ab1 = sbase + A_TILE;
    unsigned Bb  = sbase + B_OFF;
    char* Bp = sm + B_OFF;                    // generic-space B base (FIX)

    const __nv_bfloat16* __restrict__ in = (LAYER == 2) ? g_s1 : g_s2;
    const __nv_bfloat16* __restrict__ ws = (LAYER == 2) ? g_w2s : g_w3s;

    int b  = blockIdx.y;
    int n0 = blockIdx.x * 128;
    int tid  = threadIdx.x;
    int warp = tid >> 5, lane = tid & 31;
    int wco = (warp >> 2) * 32;
    int wn  = (warp & 3) * 32;

    const __nv_bfloat16* inb = in + (size_t)b * CC * N_SP;

    int nl   = tid & 127;
    int half = tid >> 7;
    int ng  = n0 + nl;
    int tt0 = ng / MM;
    int mm0 = ng - tt0 * MM;

    float acc[2][4][4];
#pragma unroll
    for (int i = 0; i < 2; i++)
#pragma unroll
        for (int j = 0; j < 4; j++)
#pragma unroll
            for (int q = 0; q < 4; q++) acc[i][j][q] = 0.f;

    // A fill: 1536 uint4 per tap, cp.async, XOR-swizzled rows of 128B
    auto fillA = [&](int tap, unsigned Ad) {
        const uint4* wsrc = (const uint4*)(ws + (size_t)tap * 3 * CC * CC);
#pragma unroll
        for (int r = 0; r < 6; r++) {
            int i = tid + r * 256;
            int row = i >> 3, q = i & 7;
            unsigned dst = Ad + row * 128 + ((q ^ (row & 7)) << 4);
            cp_async16(dst, wsrc + i);
        }
        CP_COMMIT();
    };

    // B fill: shifted-plane gather into swizzled [ci][n] tile (single buffer)
    auto fillB = [&](int tap) {
        int kt = tap / 3, km = tap - kt * 3;
        int tt = tt0 + DT * kt - PT;
        int mm = mm0 + DM * km - PM;
        bool p = (tt >= 0) & (tt < TT_) & (mm >= 0) & (mm < MM);
        const __nv_bfloat16* src = inb + (size_t)(half * 32) * N_SP + (tt * MM + mm);
        unsigned segsw = ((unsigned)(nl >> 3) << 4);
        unsigned inoff = ((unsigned)(nl & 7) << 1);
        if (p) {
#pragma unroll
            for (int c = 0; c < 32; c++) {
                int ci = half * 32 + c;
                unsigned off = ci * 256 + (segsw ^ ((unsigned)(ci & 7) << 4)) + inoff;
                *(__nv_bfloat16*)(Bp + off) = src[(size_t)c * N_SP];
            }
        } else {
            const __nv_bfloat16 z = __float2bfloat16(0.f);
#pragma unroll
            for (int c = 0; c < 32; c++) {
                int ci = half * 32 + c;
                unsigned off = ci * 256 + (segsw ^ ((unsigned)(ci & 7) << 4)) + inoff;
                *(__nv_bfloat16*)(Bp + off) = z;
            }
        }
    };

    auto domma = [&](unsigned Ad) {
#pragma unroll
        for (int ks = 0; ks < 4; ks++) {
            unsigned bf[4][2];
#pragma unroll
            for (int g = 0; g < 2; g++) {
                int ci = ks * 16 + (lane & 15);
                int nseg = (wn >> 3) + g * 2 + (lane >> 4);
                unsigned addr = Bb + ci * 256 + (((unsigned)(nseg ^ (ci & 7))) << 4);
                unsigned q0, q1, q2, q3;
                ldsm_x4_t(addr, q0, q1, q2, q3);
                bf[2 * g][0] = q0; bf[2 * g][1] = q1;
                bf[2 * g + 1][0] = q2; bf[2 * g + 1][1] = q3;
            }
#pragma unroll
            for (int s = 0; s < 3; s++) {
#pragma unroll
                for (int mf = 0; mf < 2; mf++) {
                    int row = s * 64 + wco + mf * 16 + (lane & 15);
                    int j = ks * 2 + (lane >> 4);
                    unsigned addr = Ad + row * 128 + (((unsigned)(j ^ (row & 7))) << 4);
                    unsigned a[4];
                    ldsm_x4(addr, a[0], a[1], a[2], a[3]);
#pragma unroll
                    for (int nf = 0; nf < 4; nf++)
                        mma16816(acc[mf][nf], a, bf[nf]);
                }
            }
        }
    };

    fillA(0, Ab0);
#pragma unroll 1
    for (int tap = 0; tap < 12; tap++) {
        unsigned Acur = (tap & 1) ? Ab1 : Ab0;
        fillB(tap);                                   // B free: post-mma barrier passed
        if (tap < 11) {
            fillA(tap + 1, (tap & 1) ? Ab0 : Ab1);    // other A buffer
            CP_WAIT1();                               // A(tap) complete, A(tap+1) in flight
        } else {
            CP_WAIT0();
        }
        __syncthreads();                              // A(tap)+B(tap) visible
        domma(Acur);
        __syncthreads();                              // B reads done -> next fillB safe
    }

    int lrow = lane >> 2, lk = (lane & 3) * 2;
    float* outb = g_u + (size_t)b * CC * N_SP;
#pragma unroll
    for (int mf = 0; mf < 2; mf++) {
#pragma unroll
        for (int nf = 0; nf < 4; nf++) {
            int co = wco + mf * 16 + lrow;
            int n  = n0 + wn + nf * 8 + lk;
            float* p1 = outb + (size_t)co * N_SP + n;
            float* p2 = outb + (size_t)(co + 8) * N_SP + n;
            if (n + 1 < N_SP) {
                *(float2*)p1 = make_float2(acc[mf][nf][0], acc[mf][nf][1]);
                *(float2*)p2 = make_float2(acc[mf][nf][2], acc[mf][nf][3]);
            } else if (n < N_SP) {
                p1[0] = acc[mf][nf][0];
                p2[0] = acc[mf][nf][2];
            }
        }
    }
}

// ---------------------------------------------------------------------------
// LIF over t with MLP=8 load batching. Writes bf16 spikes to g_s2.
// ---------------------------------------------------------------------------
__global__ void lif2_kernel() {
    int idx = blockIdx.x * blockDim.x + threadIdx.x;
    if (idx >= LANES) return;
    int m = idx % MM;
    int bc = idx / MM;
    const float* up = g_u + (size_t)bc * N_SP + m;
    __nv_bfloat16* sp = g_s2 + (size_t)bc * N_SP + m;
    float v = 0.f;
#pragma unroll 1
    for (int t = 0; t < 128; t += 8) {
        float xr[8];
#pragma unroll
        for (int j = 0; j < 8; j++) xr[j] = up[(t + j) * MM];
        __nv_bfloat16 sr[8];
#pragma unroll
        for (int j = 0; j < 8; j++) {
            v = v + (xr[j] - v) / TAUF;
            sr[j] = __float2bfloat16((v >= 1.f) ? 1.f : 0.f);
            v = (v >= 1.f) ? 0.f : v;
        }
#pragma unroll
        for (int j = 0; j < 8; j++) sp[(t + j) * MM] = sr[j];
    }
    {   // t = 128
        float x0 = up[128 * MM];
        v = v + (x0 - v) / TAUF;
        sp[128 * MM] = __float2bfloat16((v >= 1.f) ? 1.f : 0.f);
    }
}

// ---------------------------------------------------------------------------
// LIF3 fused with time-sum (MLP=8): writes g_ssum directly.
// ---------------------------------------------------------------------------
__global__ void lif3_tsum_kernel() {
    int idx = blockIdx.x * blockDim.x + threadIdx.x;
    if (idx >= LANES) return;
    int m = idx % MM;
    int bc = idx / MM;
    const float* up = g_u + (size_t)bc * N_SP + m;
    float v = 0.f, a = 0.f;
#pragma unroll 1
    for (int t = 0; t < 128; t += 8) {
        float xr[8];
#pragma unroll
        for (int j = 0; j < 8; j++) xr[j] = up[(t + j) * MM];
#pragma unroll
        for (int j = 0; j < 8; j++) {
            v = v + (xr[j] - v) / TAUF;
            if (v >= 1.f) { a += 1.f; v = 0.f; }
        }
    }
    {
        float x0 = up[128 * MM];
        v = v + (x0 - v) / TAUF;
        if (v >= 1.f) a += 1.f;
    }
    g_ssum[(size_t)bc * MM + m] = a;
}

// ---------------------------------------------------------------------------
__global__ void fc_kernel(const float* __restrict__ wf,
                          const float* __restrict__ bf,
                          float* __restrict__ y) {
    int b = blockIdx.x, j = blockIdx.y;
    int tid = threadIdx.x;
    const float* sb = g_ssum + b * (CC * MM);
    const float* wj = wf + j * (CC * MM);
    float acc = 0.f;
    for (int i = tid; i < CC * MM; i += 128) acc += sb[i] * wj[i];
    __shared__ float red[128];
    red[tid] = acc;
    __syncthreads();
    for (int s = 64; s > 0; s >>= 1) {
        if (tid < s) red[tid] += red[tid + s];
        __syncthreads();
    }
    if (tid == 0) y[b * 12 + j] = red[0] * (1.0f / 129.0f) + bf[j];
}

// ---------------------------------------------------------------------------
extern "C" void kernel_launch(void* const* d_in, const int* in_sizes, int n_in,
                              void* d_out, int out_size) {
    const float* x  = (const float*)d_in[0];
    const float* w1 = (const float*)d_in[1];
    const float* w2 = (const float*)d_in[2];
    const float* w3 = (const float*)d_in[3];
    const float* wf = (const float*)d_in[4];
    const float* bf = (const float*)d_in[5];
    float* y = (float*)d_out;

    static int smem_set = 0;
    if (!smem_set) {
        cudaFuncSetAttribute(conv_mma_kernel<2, 4, 6, 3, 3>,
                             cudaFuncAttributeMaxDynamicSharedMemorySize, SMEM_BYTES);
        cudaFuncSetAttribute(conv_mma_kernel<3, 16, 24, 9, 9>,
                             cudaFuncAttributeMaxDynamicSharedMemorySize, SMEM_BYTES);
        smem_set = 1;
    }

    {
        dim3 grid((CC * CC * 12 + 255) / 256, 2);
        wsplit_kernel<<<grid, 256>>>(w2, w3);
    }

    conv1_lif_kernel<<<(LANES + 255) / 256, 256>>>(x, w1);

    {
        dim3 grid((N_SP + 127) / 128, BB);
        conv_mma_kernel<2, 4, 6, 3, 3><<<grid, 256, SMEM_BYTES>>>();
    }
    lif2_kernel<<<(LANES + 255) / 256, 256>>>();

    {
        dim3 grid((N_SP + 127) / 128, BB);
        conv_mma_kernel<3, 16, 24, 9, 9><<<grid, 256, SMEM_BYTES>>>();
    }
    lif3_tsum_kernel<<<(LANES + 255) / 256, 256>>>();

    {
        dim3 grid(BB, 12);
        fc_kernel<<<grid, 128>>>(wf, bf, y);
    }
}